// round 10
// baseline (speedup 1.0000x reference)
#include <cuda_runtime.h>
#include <cuda_fp16.h>
#include <cstdint>
#include <math.h>

// Histogram2D via first-moment particle deposit + exact separable erf-CDF
// convolution with derivative correction, q=4 fine cells per bin.
// THREE kernels total (launch floors dominate at this scale):
//   1) k_deposit: 2 REDs/point into 8-byte fine cells; one extra block builds
//      the W/W' tap tables and the Cw/Cwp sum-coefficient tables, resets g_sum.
//   2) k_pass1: reduce fx -> (Ba,Bb)[ix][fy]; each CTA also contributes its
//      exact share of the final normalization sum (one atomicAdd per CTA).
//   3) k_pass2: reduce fy, scale by 1/(g_sum*dx*dy) inline, write out, and
//      re-zero the fine grid for the next graph replay (device globals are
//      zero-initialized, so the first call is also correct).
// Error model (validated R7/R8/R9): ~1.46e-4 at q=4 with f16 moments.

#define NB    128
#define Q     4
#define PADB  8                     // padding in bins
#define PAD   (PADB*Q)              // 32 fine cells
#define NF    (NB*Q + 2*PAD)        // 576 fine cells per axis
#define TAP0  12                    // first tap (zc = -4.875 bins)
#define NTAP  44                    // support ~ +/-5 bins (tail < 3e-7)
#define ISEG  8                     // ix outputs per pass1 CTA
#define ERANGE (Q*ISEG + NTAP - Q)  // 72 fine rows read per pass1 CTA

__device__ float4 g_fg4[(NF * NF) / 2]; // fine grid, 2 cells per float4, 2.65 MB
__device__ float2 g_Bt2[NB * NF];       // pass1 output (Ba,Bb)[ix][fy], 590 KB
__device__ float  g_W[64];              // kernel tap table (bin units)
__device__ float  g_Wp[64];             // d/dz of tap table
__device__ float  g_Cw[NF];             // Cw[fy]  = sum_iy W (fy - Q*iy - TAP0)
__device__ float  g_Cwp[NF];            // Cwp[fy] = sum_iy W'(fy - Q*iy - TAP0)
__device__ float  g_sum;

// ---------------------------------------------------------------------------
// Kernel 1: deposit (blocks [0, NPB)) + table block (last block).
__global__ __launch_bounds__(256)
void k_deposit(const float* __restrict__ x,
               const float* __restrict__ ex,
               const float* __restrict__ ey,
               int n)
{
    if (blockIdx.x == gridDim.x - 1) {
        // ---- table block: W/W', then Cw/Cwp, then reset g_sum ----
        const int tid = threadIdx.x;
        if (tid < 64) {
            float zc = ((float)tid + 0.5f) * (1.0f / (float)Q) - (float)PADB;
            const float is2 = 0.70710678118654752f;     // 1/sqrt(2), sigma=1 bin
            g_W[tid] = 0.5f * (erff((1.0f - zc) * is2) - erff((-zc) * is2));
            const float inv_s2pi = 0.3989422804014327f; // 1/sqrt(2*pi)
            g_Wp[tid] = inv_s2pi * (expf(-0.5f * zc * zc)
                                  - expf(-0.5f * (1.0f - zc) * (1.0f - zc)));
        }
        if (tid == 64) g_sum = 0.0f;
        __syncthreads();
        for (int fy = tid; fy < NF; fy += 256) {
            float cw = 0.f, cwp = 0.f;
            #pragma unroll 4
            for (int iy = 0; iy < NB; iy++) {
                int t = fy - Q * iy - TAP0;
                if (t >= 0 && t < NTAP) {
                    cw  += g_W[TAP0 + t];
                    cwp += g_Wp[TAP0 + t];
                }
            }
            g_Cw[fy]  = cw;
            g_Cwp[fy] = cwp;
        }
        return;
    }

    const float lox = ex[0], dx = ex[1] - ex[0];
    const float loy = ey[0], dy = ey[1] - ey[0];
    const float sx = (float)Q / dx;
    const float sy = (float)Q / dy;

    int p = blockIdx.x * blockDim.x + threadIdx.x;
    if (p >= n) return;

    float2 u = *reinterpret_cast<const float2*>(x + (size_t)p * 6);

    float pfx = (u.x - lox) * sx + (float)PAD;
    float pfy = (u.y - loy) * sy + (float)PAD;
    float cfx = floorf(pfx), cfy = floorf(pfy);
    int cx = (int)cfx, cy = (int)cfy;
    if ((unsigned)cx >= NF || (unsigned)cy >= NF) return;  // mass < 1e-8

    float dxb = (pfx - cfx - 0.5f) * (1.0f / (float)Q);    // bin units
    float dyb = (pfy - cfy - 0.5f) * (1.0f / (float)Q);

    char* cell = reinterpret_cast<char*>(g_fg4) + ((size_t)cx * NF + cy) * 8;
    asm volatile("red.global.add.f32 [%0], %1;"
                 :: "l"(cell), "f"(1.0f) : "memory");
    __half2 hm = __halves2half2(__float2half(dyb), __float2half(dxb));
    asm volatile("red.global.add.noftz.f16x2 [%0], %1;"
                 :: "l"(cell + 4), "r"(*reinterpret_cast<uint32_t*>(&hm))
                 : "memory");
}

// ---------------------------------------------------------------------------
// Kernel 2: reduce fx; halo-redundant reads, no atomics on Bt, no Bt zeroing.
// Also accumulates this CTA's exact share of the final sum into g_sum.
__global__ __launch_bounds__(64)
void k_pass1()
{
    __shared__ float sW[NTAP], sWp[NTAP];
    __shared__ float sred[64];
    if (threadIdx.x < NTAP) {
        sW[threadIdx.x]  = g_W[TAP0 + threadIdx.x];
        sWp[threadIdx.x] = g_Wp[TAP0 + threadIdx.x];
    }
    __syncthreads();

    const int fy = blockIdx.y * 64 + threadIdx.x;   // < NF (9*64 = 576)
    const int I0 = blockIdx.x * ISEG;
    const float2* col = reinterpret_cast<const float2*>(g_fg4) + fy;

    float2 acc[ISEG];
    #pragma unroll
    for (int s = 0; s < ISEG; s++) acc[s] = make_float2(0.f, 0.f);

    #pragma unroll 4
    for (int e = 0; e < ERANGE; e++) {
        const int fx = I0 * Q + TAP0 + e;           // max 563 < NF
        float2 M = col[(size_t)fx * NF];
        uint32_t mb = __float_as_uint(M.y);
        __half2 h2 = *reinterpret_cast<__half2*>(&mb);
        float2 mom = __half22float2(h2);            // mom.x = M01, mom.y = M10
        #pragma unroll
        for (int s = 0; s < ISEG; s++) {
            int t = e - Q * s;                      // tap offset from TAP0
            if (t >= 0 && t < NTAP) {
                acc[s].x = fmaf(sW[t], M.x, fmaf(sWp[t], mom.y, acc[s].x));
                acc[s].y = fmaf(sW[t], mom.x, acc[s].y);
            }
        }
    }

    float pa = 0.f, pb = 0.f;
    #pragma unroll
    for (int s = 0; s < ISEG; s++) {
        g_Bt2[(size_t)(I0 + s) * NF + fy] = acc[s];
        pa += acc[s].x;
        pb += acc[s].y;
    }

    // CTA's contribution to the global normalization sum.
    sred[threadIdx.x] = g_Cw[fy] * pa + g_Cwp[fy] * pb;
    __syncthreads();
    #pragma unroll
    for (int off = 32; off > 0; off >>= 1) {
        if (threadIdx.x < off) sred[threadIdx.x] += sred[threadIdx.x + off];
        __syncthreads();
    }
    if (threadIdx.x == 0) atomicAdd(&g_sum, sred[0]);
}

// ---------------------------------------------------------------------------
// Kernel 3: reduce fy, scale inline (g_sum final at launch), zero g_fg for the
// next replay. One CTA per ix; Bt row staged in padded smem (conflict-free).
#define SPAD(i) ((i) + ((i) >> 2))
__global__ __launch_bounds__(128)
void k_pass2(float* __restrict__ out,
             const float* __restrict__ ex,
             const float* __restrict__ ey)
{
    __shared__ float sW[NTAP], sWp[NTAP];
    __shared__ float sBa[NF + NF / 4], sBb[NF + NF / 4];
    __shared__ float s_scale;

    const int iy = threadIdx.x;
    const int ix = blockIdx.x;

    if (iy < NTAP) { sW[iy] = g_W[TAP0 + iy]; sWp[iy] = g_Wp[TAP0 + iy]; }
    if (iy == 127) {
        float dxw = ex[1] - ex[0];
        float dyw = ey[1] - ey[0];
        s_scale = 1.0f / (g_sum * dxw * dyw);
    }
    const float2* brow = g_Bt2 + (size_t)ix * NF;
    #pragma unroll
    for (int i = iy; i < NF; i += 128) {
        float2 v = brow[i];
        sBa[SPAD(i)] = v.x;
        sBb[SPAD(i)] = v.y;
    }
    __syncthreads();

    const int base = Q * iy + TAP0;                 // max fy index 563 < NF
    float a0 = 0.f, a1 = 0.f, a2 = 0.f, a3 = 0.f;
    #pragma unroll
    for (int t = 0; t < NTAP; t += 4) {
        a0 = fmaf(sW[t+0], sBa[SPAD(base+t+0)], fmaf(sWp[t+0], sBb[SPAD(base+t+0)], a0));
        a1 = fmaf(sW[t+1], sBa[SPAD(base+t+1)], fmaf(sWp[t+1], sBb[SPAD(base+t+1)], a1));
        a2 = fmaf(sW[t+2], sBa[SPAD(base+t+2)], fmaf(sWp[t+2], sBb[SPAD(base+t+2)], a2));
        a3 = fmaf(sW[t+3], sBa[SPAD(base+t+3)], fmaf(sWp[t+3], sBb[SPAD(base+t+3)], a3));
    }
    out[(size_t)ix * NB + iy] = ((a0 + a1) + (a2 + a3)) * s_scale;

    // Re-zero the fine grid for the next replay (coalesced float4 stores).
    const float4 z = make_float4(0.f, 0.f, 0.f, 0.f);
    const int gt = ix * 128 + iy;
    for (int i = gt; i < (NF * NF) / 2; i += NB * 128) g_fg4[i] = z;
}

// ---------------------------------------------------------------------------
extern "C" void kernel_launch(void* const* d_in, const int* in_sizes, int n_in,
                              void* d_out, int out_size)
{
    const float* x  = (const float*)d_in[0];
    const float* ex = (const float*)d_in[1];
    const float* ey = (const float*)d_in[2];
    float* out = (float*)d_out;

    int n = in_sizes[0] / 6;

    k_deposit<<<(n + 255) / 256 + 1, 256>>>(x, ex, ey, n);
    k_pass1<<<dim3(NB / ISEG, NF / 64), 64>>>();
    k_pass2<<<NB, 128>>>(out, ex, ey);
}